// round 13
// baseline (speedup 1.0000x reference)
#include <cuda_runtime.h>
#include <cuda_fp16.h>
#include <math.h>
#include <stdint.h>

#define TDIM 2048
#define CDIM 1024
#define HN   8
#define NW   8192
#define WIN  320
#define KQ   384
#define TT   64
#define NTIL 32
#define GAMMA 0.96875f

// fp16 operands, all single precision.
__device__ __half g_Xh[(size_t)TDIM * CDIM];
__device__ __half g_Wth[(size_t)3 * NW * CDIM];            // [z][n][k]
__device__ __half g_Qh[(size_t)HN * TDIM * CDIM];
__device__ __half g_Kh[(size_t)HN * TDIM * CDIM];
__device__ __half g_Vh[(size_t)HN * TDIM * CDIM];          // [h][t][c]
__device__ __half g_Vth[(size_t)HN * CDIM * TDIM];         // [h][c][t]
__device__ __half g_Ph[(size_t)HN * NTIL * TT * KQ];       // [h][tile][t][q]

// ---------------------------------------------------------------------------
#define CP16(dst, src) \
    asm volatile("cp.async.cg.shared.global [%0], [%1], 16;" :: "r"(dst), "l"(src))
#define CP16Z(dst, src, sz) \
    asm volatile("cp.async.cg.shared.global [%0], [%1], 16, %2;" :: "r"(dst), "l"(src), "r"(sz))
#define CP_COMMIT() asm volatile("cp.async.commit_group;" ::: "memory")
#define CP_WAIT1()  asm volatile("cp.async.wait_group 1;" ::: "memory")
#define CP_WAIT0()  asm volatile("cp.async.wait_group 0;" ::: "memory")

__device__ __forceinline__ uint32_t smem_u32(const void* p) {
    uint32_t a;
    asm("{ .reg .u64 t; cvta.to.shared.u64 t, %1; cvt.u32.u64 %0, t; }"
        : "=r"(a) : "l"(p));
    return a;
}

__device__ __forceinline__ void mma_f16(float c[4], const uint32_t a[4],
                                        const uint32_t b[2]) {
    asm volatile(
        "mma.sync.aligned.m16n8k16.row.col.f32.f16.f16.f32 "
        "{%0,%1,%2,%3}, {%4,%5,%6,%7}, {%8,%9}, {%0,%1,%2,%3};"
        : "+f"(c[0]), "+f"(c[1]), "+f"(c[2]), "+f"(c[3])
        : "r"(a[0]), "r"(a[1]), "r"(a[2]), "r"(a[3]), "r"(b[0]), "r"(b[1]));
}

// fp16-accumulate variant (2x rate on most mma.sync implementations)
__device__ __forceinline__ void mma_h16(uint32_t c[2], const uint32_t a[4],
                                        const uint32_t b[2]) {
    asm volatile(
        "mma.sync.aligned.m16n8k16.row.col.f16.f16.f16.f16 "
        "{%0,%1}, {%2,%3,%4,%5}, {%6,%7}, {%0,%1};"
        : "+r"(c[0]), "+r"(c[1])
        : "r"(a[0]), "r"(a[1]), "r"(a[2]), "r"(a[3]), "r"(b[0]), "r"(b[1]));
}

__device__ __forceinline__ uint32_t pack_h2(float v0, float v1) {
    __half2 h = __floats2half2_rn(v0, v1);
    return *(uint32_t*)&h;
}

// ---------------------------------------------------------------------------
// Prep: X -> fp16
// ---------------------------------------------------------------------------
__global__ __launch_bounds__(256) void prep_x(const float* __restrict__ X)
{
    int i = blockIdx.x * 256 + threadIdx.x;
    float4 v = ((const float4*)X)[i];
    ((uint2*)g_Xh)[i] = make_uint2(pack_h2(v.x, v.y), pack_h2(v.z, v.w));
}

// ---------------------------------------------------------------------------
// Prep: transpose W [K,N] -> Wt [N,K], fp16
// ---------------------------------------------------------------------------
__global__ __launch_bounds__(256) void prep_w(
    const float* __restrict__ Wq, const float* __restrict__ Wk,
    const float* __restrict__ Wv)
{
    const int z = blockIdx.z;
    const float* W = (z == 0) ? Wq : ((z == 1) ? Wk : Wv);
    const int n0 = blockIdx.x * 32;
    const int k0 = blockIdx.y * 32;

    __shared__ float t[32][33];
    const int tx = threadIdx.x, ty = threadIdx.y;
#pragma unroll
    for (int j = 0; j < 4; j++)
        t[ty + 8 * j][tx] = W[(size_t)(k0 + ty + 8 * j) * NW + n0 + tx];
    __syncthreads();
#pragma unroll
    for (int j = 0; j < 4; j++) {
        float v = t[tx][ty + 8 * j];
        size_t o = ((size_t)z * NW + n0 + ty + 8 * j) * CDIM + k0 + tx;
        g_Wth[o] = __float2half_rn(v);
    }
}

// ---------------------------------------------------------------------------
// Projection: fp16 x fp16 with fp16 ACCUMULATE (chunked: promote to fp32
// every 2 stages = K=64), fused RoPE+SiLU.  CTA 128x128, Kstage=32, occ-2.
// ---------------------------------------------------------------------------
#define PSTAGE 20480
#define SMEM_PROJ (3 * PSTAGE)

__device__ __forceinline__ void proj_load_stage(
    uint32_t stb, int tid, int m0, int zn0, int k0)
{
#pragma unroll
    for (int i = 0; i < 4; i++) {
        const int c = tid + i * 256;
        if (c < 512) {
            const int row = c >> 2;
            const int ch  = c & 3;
            const __half* src = g_Xh + (size_t)(m0 + row) * CDIM + k0 + ch * 8;
            CP16(stb + row * 80 + ch * 16, src);
        } else {
            const int rem = c - 512;
            const int row = rem >> 2;
            const int ch  = rem & 3;
            const __half* src = g_Wth + (size_t)(zn0 + row) * CDIM + k0 + ch * 8;
            CP16(stb + 10240 + row * 80 + ch * 16, src);
        }
    }
}

__global__ __launch_bounds__(256, 2) void proj_mma()
{
    extern __shared__ char smem[];
    const uint32_t sb = smem_u32(smem);
    const int tid = threadIdx.x;
    const int wid = tid >> 5;
    const int lane = tid & 31;
    const int wm = wid & 1, wn = wid >> 1;
    const int g = lane >> 2, t4 = lane & 3;

    const int m0 = blockIdx.x * 128;
    const int n0 = blockIdx.y * 128;
    const int z  = blockIdx.z;
    const int zn0 = z * NW + n0;

    float acc[4][4][4];
    uint32_t hacc[4][4][2];
#pragma unroll
    for (int i = 0; i < 4; i++)
#pragma unroll
        for (int j = 0; j < 4; j++) {
#pragma unroll
            for (int q = 0; q < 4; q++) acc[i][j][q] = 0.f;
            hacc[i][j][0] = 0u; hacc[i][j][1] = 0u;
        }

    proj_load_stage(sb, tid, m0, zn0, 0);
    CP_COMMIT();
    proj_load_stage(sb + PSTAGE, tid, m0, zn0, 32);
    CP_COMMIT();

#pragma unroll 1
    for (int s = 0; s < 32; s++) {
        if (s < 31) { CP_WAIT1(); } else { CP_WAIT0(); }
        __syncthreads();
        if (s + 2 < 32) {
            proj_load_stage(sb + ((s + 2) % 3) * PSTAGE, tid, m0, zn0, (s + 2) * 32);
            CP_COMMIT();
        }
        const char* st = smem + (s % 3) * PSTAGE;
        const char* Ah = st;
        const char* Bh = st + 10240;

#pragma unroll
        for (int kk = 0; kk < 32; kk += 16) {
            uint32_t bh[4][2];
#pragma unroll
            for (int j = 0; j < 4; j++) {
                const int bb = (wn * 32 + j * 8 + g) * 80 + kk * 2 + t4 * 4;
                bh[j][0] = *(const uint32_t*)(Bh + bb);
                bh[j][1] = *(const uint32_t*)(Bh + bb + 16);
            }
#pragma unroll
            for (int i = 0; i < 4; i++) {
                uint32_t a[4];
                const int b0 = (wm * 64 + i * 16 + g) * 80 + kk * 2 + t4 * 4;
                a[0] = *(const uint32_t*)(Ah + b0);
                a[1] = *(const uint32_t*)(Ah + b0 + 640);
                a[2] = *(const uint32_t*)(Ah + b0 + 16);
                a[3] = *(const uint32_t*)(Ah + b0 + 656);
#pragma unroll
                for (int j = 0; j < 4; j++)
                    mma_h16(hacc[i][j], a, bh[j]);
            }
        }

        // promote fp16 accumulators -> fp32 every 2 stages (K=64 chunk)
        if ((s & 1) == 1) {
#pragma unroll
            for (int i = 0; i < 4; i++)
#pragma unroll
                for (int j = 0; j < 4; j++) {
                    float2 lo = __half22float2(*(__half2*)&hacc[i][j][0]);
                    float2 hi = __half22float2(*(__half2*)&hacc[i][j][1]);
                    acc[i][j][0] += lo.x; acc[i][j][1] += lo.y;
                    acc[i][j][2] += hi.x; acc[i][j][3] += hi.y;
                    hacc[i][j][0] = 0u;   hacc[i][j][1] = 0u;
                }
        }
    }

    // epilogue: RoPE (Q,K cols<64) + SiLU, fp16 store
    const int h  = n0 >> 10;
    const int cbase = (n0 & 1023) + wn * 32 + 2 * t4;
    const bool rope_blk = (z < 2) && ((n0 & 1023) == 0) && (wn < 2);

    __half* Hi = (z == 0) ? g_Qh : ((z == 1) ? g_Kh : g_Vh);
    Hi += (size_t)h * TDIM * CDIM;

#pragma unroll
    for (int i = 0; i < 4; i++) {
#pragma unroll
        for (int rr = 0; rr < 2; rr++) {
            const int r = m0 + wm * 64 + i * 16 + g + rr * 8;
#pragma unroll
            for (int j = 0; j < 4; j++) {
                const int col = cbase + j * 8;
                float v0 = acc[i][j][2 * rr];
                float v1 = acc[i][j][2 * rr + 1];
                if (rope_blk) {
                    int c2 = col >> 1;
                    float invf = (float)exp(-((double)(2 * c2) / 64.0) * log(10000.0));
                    float ang = (float)r * invf;
                    float sn, cs;
                    sincosf(ang, &sn, &cs);
                    float y0 = v0 * cs - v1 * sn;
                    float y1 = v1 * cs + v0 * sn;
                    v0 = y0; v1 = y1;
                }
                v0 = v0 / (1.f + expf(-v0));
                v1 = v1 / (1.f + expf(-v1));
                ((uint32_t*)Hi)[((size_t)r * CDIM + col) >> 1] = pack_h2(v0, v1);
            }
        }
    }
}

// ---------------------------------------------------------------------------
// V transpose: [h][t][c] -> [h][c][t]
// ---------------------------------------------------------------------------
__global__ void transpose_v()
{
    __shared__ unsigned short sh[32][33];
    const int c0 = blockIdx.x * 32;
    const int t0 = blockIdx.y * 32;
    const int h  = blockIdx.z;
    const int tx = threadIdx.x, ty = threadIdx.y;

    const unsigned short* Vh = (const unsigned short*)g_Vh + (size_t)h * TDIM * CDIM;
#pragma unroll
    for (int k = 0; k < 4; k++) {
        int r = ty + 8 * k;
        sh[r][tx] = Vh[(size_t)(t0 + r) * CDIM + c0 + tx];
    }
    __syncthreads();
    unsigned short* Th = (unsigned short*)g_Vth + (size_t)h * CDIM * TDIM;
#pragma unroll
    for (int k = 0; k < 4; k++) {
        int r = ty + 8 * k;
        Th[(size_t)(c0 + r) * TDIM + t0 + tx] = sh[tx][r];
    }
}

// ---------------------------------------------------------------------------
// qk_mma: P = decay * (K Q^T), single-term fp16, Kstage=64.  (R12 shape.)
// ---------------------------------------------------------------------------
#define QKSTAGE 27648
#define SMEM_QK (3 * QKSTAGE)

__global__ __launch_bounds__(256, 2) void qk_mma()
{
    extern __shared__ char smem[];
    const uint32_t sb = smem_u32(smem);
    const int tid = threadIdx.x;
    const int wid = tid >> 5;
    const int lane = tid & 31;
    const int wm = wid & 1, wn = wid >> 1;
    const int g = lane >> 2, t4 = lane & 3;

    const int qc   = blockIdx.x;          // 0..2
    const int tile = blockIdx.y;
    const int h    = blockIdx.z;
    const int t0   = tile * TT;
    const int q0   = t0 + qc * 128;

    const __half* Kh = g_Kh + (size_t)h * TDIM * CDIM;
    const __half* Qh = g_Qh + (size_t)h * TDIM * CDIM;

    float acc[2][4][4];
#pragma unroll
    for (int i = 0; i < 2; i++)
#pragma unroll
        for (int j = 0; j < 4; j++)
#pragma unroll
            for (int q = 0; q < 4; q++) acc[i][j][q] = 0.f;

    auto load_stage = [&](int s, uint32_t stb) {
        const int k0 = s * 64;
#pragma unroll
        for (int i = 0; i < 6; i++) {
            const int c = tid + i * 256;
            if (c < 512) {
                const int row = c >> 3, ch = c & 7;
                const __half* src = Kh + (size_t)(t0 + row) * CDIM + k0 + ch * 8;
                CP16(stb + row * 144 + ch * 16, src);
            } else {
                const int rem = c - 512;
                const int row = rem >> 3, ch = rem & 7;
                int q = q0 + row;
                int sz = (q < TDIM) ? 16 : 0;
                if (q >= TDIM) q = 0;
                const __half* src = Qh + (size_t)q * CDIM + k0 + ch * 8;
                CP16Z(stb + 9216 + row * 144 + ch * 16, src, sz);
            }
        }
    };

    load_stage(0, sb);
    CP_COMMIT();
    load_stage(1, sb + QKSTAGE);
    CP_COMMIT();

#pragma unroll 1
    for (int s = 0; s < 16; s++) {
        if (s < 15) { CP_WAIT1(); } else { CP_WAIT0(); }
        __syncthreads();
        if (s + 2 < 16) {
            load_stage(s + 2, sb + ((s + 2) % 3) * QKSTAGE);
            CP_COMMIT();
        }
        const char* st = smem + (s % 3) * QKSTAGE;
        const char* Ah = st;
        const char* Bh = st + 9216;

#pragma unroll
        for (int kk = 0; kk < 64; kk += 16) {
            uint32_t ah[2][4];
#pragma unroll
            for (int i = 0; i < 2; i++) {
                const int b0 = (wm * 32 + i * 16 + g) * 144 + kk * 2 + t4 * 4;
                ah[i][0] = *(const uint32_t*)(Ah + b0);
                ah[i][1] = *(const uint32_t*)(Ah + b0 + 1152);
                ah[i][2] = *(const uint32_t*)(Ah + b0 + 16);
                ah[i][3] = *(const uint32_t*)(Ah + b0 + 1168);
            }
            uint32_t bh[4][2];
#pragma unroll
            for (int j = 0; j < 4; j++) {
                const int bb = (wn * 32 + j * 8 + g) * 144 + kk * 2 + t4 * 4;
                bh[j][0] = *(const uint32_t*)(Bh + bb);
                bh[j][1] = *(const uint32_t*)(Bh + bb + 16);
            }
#pragma unroll
            for (int i = 0; i < 2; i++)
#pragma unroll
                for (int j = 0; j < 4; j++)
                    mma_f16(acc[i][j], ah[i], bh[j]);
        }
    }

    // epilogue: decay + mask, fp16 store P
    const float lg = log2f(GAMMA);
    __half* Phb = g_Ph + ((size_t)h * NTIL + tile) * TT * KQ;
#pragma unroll
    for (int i = 0; i < 2; i++) {
#pragma unroll
        for (int rr = 0; rr < 2; rr++) {
            const int tl = wm * 32 + i * 16 + g + rr * 8;
            const int t  = t0 + tl;
#pragma unroll
            for (int j = 0; j < 4; j++) {
                const int ql = qc * 128 + wn * 32 + j * 8 + 2 * t4;
                const int q  = t0 + ql;
                float v0 = acc[i][j][2 * rr];
                float v1 = acc[i][j][2 * rr + 1];
                int wd0 = q - t, wd1 = wd0 + 1;
                v0 = (wd0 >= 0 && wd0 < WIN && q < TDIM)
                     ? v0 * exp2f((float)wd0 * lg) : 0.f;
                v1 = (wd1 >= 0 && wd1 < WIN && (q + 1) < TDIM)
                     ? v1 * exp2f((float)wd1 * lg) : 0.f;
                ((uint32_t*)Phb)[((size_t)tl * KQ + ql) >> 1] = pack_h2(v0, v1);
            }
        }
    }
}

// ---------------------------------------------------------------------------
// av_mma: out[t][c] = sum_{h,q} P * V, single-term fp16, Kstage=64. (R12.)
// ---------------------------------------------------------------------------
#define AVSTAGE 27648
#define SMEM_AV (3 * AVSTAGE)

__global__ __launch_bounds__(256, 2) void av_mma(float* __restrict__ out)
{
    extern __shared__ char smem[];
    const uint32_t sb = smem_u32(smem);
    const int tid = threadIdx.x;
    const int wid = tid >> 5;
    const int lane = tid & 31;
    const int wm = wid & 1, wn = wid >> 1;
    const int g = lane >> 2, t4 = lane & 3;

    const int cc   = blockIdx.x;      // 0..7
    const int tile = blockIdx.y;
    const int t0   = tile * TT;
    const int c0   = cc * 128;

    float acc[2][4][4];
#pragma unroll
    for (int i = 0; i < 2; i++)
#pragma unroll
        for (int j = 0; j < 4; j++)
#pragma unroll
            for (int q = 0; q < 4; q++) acc[i][j][q] = 0.f;

    auto load_stage = [&](int s, uint32_t stb) {
        const int kk0 = s * 64;
        const int h   = kk0 / KQ;
        const int ql  = kk0 - h * KQ;
#pragma unroll
        for (int i = 0; i < 6; i++) {
            const int c = tid + i * 256;
            if (c < 512) {
                const int row = c >> 3, ch = c & 7;
                const __half* src = g_Ph
                    + ((size_t)h * NTIL + tile) * TT * KQ
                    + (size_t)row * KQ + ql + ch * 8;
                CP16(stb + row * 144 + ch * 16, src);
            } else {
                const int rem = c - 512;
                const int row = rem >> 3, ch = rem & 7;
                int tg = t0 + ql + ch * 8;
                int sz = (tg < TDIM) ? 16 : 0;
                if (tg >= TDIM) tg = 0;
                const __half* src = g_Vth
                    + ((size_t)h * CDIM + c0 + row) * TDIM + tg;
                CP16Z(stb + 9216 + row * 144 + ch * 16, src, sz);
            }
        }
    };

    load_stage(0, sb);
    CP_COMMIT();
    load_stage(1, sb + AVSTAGE);
    CP_COMMIT();

#pragma unroll 1
    for (int s = 0; s < 48; s++) {
        if (s < 47) { CP_WAIT1(); } else { CP_WAIT0(); }
        __syncthreads();
        if (s + 2 < 48) {
            load_stage(s + 2, sb + ((s + 2) % 3) * AVSTAGE);
            CP_COMMIT();
        }
        const char* st = smem + (s % 3) * AVSTAGE;
        const char* Ah = st;
        const char* Bh = st + 9216;

#pragma unroll
        for (int kk = 0; kk < 64; kk += 16) {
            uint32_t ah[2][4];
#pragma unroll
            for (int i = 0; i < 2; i++) {
                const int b0 = (wm * 32 + i * 16 + g) * 144 + kk * 2 + t4 * 4;
                ah[i][0] = *(const uint32_t*)(Ah + b0);
                ah[i][1] = *(const uint32_t*)(Ah + b0 + 1152);
                ah[i][2] = *(const uint32_t*)(Ah + b0 + 16);
                ah[i][3] = *(const uint32_t*)(Ah + b0 + 1168);
            }
            uint32_t bh[4][2];
#pragma unroll
            for (int j = 0; j < 4; j++) {
                const int bb = (wn * 32 + j * 8 + g) * 144 + kk * 2 + t4 * 4;
                bh[j][0] = *(const uint32_t*)(Bh + bb);
                bh[j][1] = *(const uint32_t*)(Bh + bb + 16);
            }
#pragma unroll
            for (int i = 0; i < 2; i++)
#pragma unroll
                for (int j = 0; j < 4; j++)
                    mma_f16(acc[i][j], ah[i], bh[j]);
        }
    }

    // epilogue: fp32 out
#pragma unroll
    for (int i = 0; i < 2; i++) {
#pragma unroll
        for (int rr = 0; rr < 2; rr++) {
            const int t = t0 + wm * 32 + i * 16 + g + rr * 8;
#pragma unroll
            for (int j = 0; j < 4; j++) {
                const int c = c0 + wn * 32 + j * 8 + 2 * t4;
                *(float2*)(out + (size_t)t * CDIM + c) =
                    make_float2(acc[i][j][2 * rr], acc[i][j][2 * rr + 1]);
            }
        }
    }
}

// ---------------------------------------------------------------------------
// GroupNorm in place on out
// ---------------------------------------------------------------------------
__global__ __launch_bounds__(256) void gn_kernel(
    float* __restrict__ out,
    const float* __restrict__ wgt,
    const float* __restrict__ bias)
{
    const int t = blockIdx.x;
    const int tid = threadIdx.x;

    float4 v = *(float4*)(out + (size_t)t * CDIM + tid * 4);
    float s  = v.x + v.y + v.z + v.w;
    float sq = v.x * v.x + v.y * v.y + v.z * v.z + v.w * v.w;

#pragma unroll
    for (int off = 8; off > 0; off >>= 1) {
        s  += __shfl_down_sync(0xffffffffu, s,  off, 16);
        sq += __shfl_down_sync(0xffffffffu, sq, off, 16);
    }
    s  = __shfl_sync(0xffffffffu, s,  0, 16);
    sq = __shfl_sync(0xffffffffu, sq, 0, 16);

    float mean = s * (1.f / 64.f);
    float var  = sq * (1.f / 64.f) - mean * mean;
    float rs   = rsqrtf(var + 1e-5f);

    float4 w4 = *(const float4*)(wgt + tid * 4);
    float4 b4 = *(const float4*)(bias + tid * 4);
    v.x = (v.x - mean) * rs * w4.x + b4.x;
    v.y = (v.y - mean) * rs * w4.y + b4.y;
    v.z = (v.z - mean) * rs * w4.z + b4.z;
    v.w = (v.w - mean) * rs * w4.w + b4.w;
    *(float4*)(out + (size_t)t * CDIM + tid * 4) = v;
}

// ---------------------------------------------------------------------------
extern "C" void kernel_launch(void* const* d_in, const int* in_sizes, int n_in,
                              void* d_out, int out_size)
{
    const float* X  = (const float*)d_in[0];
    const float* Wq = (const float*)d_in[1];
    const float* Wk = (const float*)d_in[2];
    const float* Wv = (const float*)d_in[3];
    const float* gw = (const float*)d_in[4];
    const float* gb = (const float*)d_in[5];
    float* out = (float*)d_out;

    prep_x<<<(TDIM * CDIM / 4) / 256, 256>>>(X);
    prep_w<<<dim3(NW / 32, CDIM / 32, 3), dim3(32, 8)>>>(Wq, Wk, Wv);

    cudaFuncSetAttribute(proj_mma, cudaFuncAttributeMaxDynamicSharedMemorySize,
                         SMEM_PROJ);
    proj_mma<<<dim3(16, 64, 3), 256, SMEM_PROJ>>>();

    transpose_v<<<dim3(CDIM / 32, TDIM / 32, HN), dim3(32, 8)>>>();

    cudaFuncSetAttribute(qk_mma, cudaFuncAttributeMaxDynamicSharedMemorySize,
                         SMEM_QK);
    qk_mma<<<dim3(3, NTIL, HN), 256, SMEM_QK>>>();

    cudaFuncSetAttribute(av_mma, cudaFuncAttributeMaxDynamicSharedMemorySize,
                         SMEM_AV);
    av_mma<<<dim3(8, NTIL), 256, SMEM_AV>>>(out);

    gn_kernel<<<TDIM, 256>>>(out, gw, gb);
}

// round 14
// speedup vs baseline: 1.1111x; 1.1111x over previous
#include <cuda_runtime.h>
#include <cuda_fp16.h>
#include <math.h>
#include <stdint.h>

#define TDIM 2048
#define CDIM 1024
#define HN   8
#define NW   8192
#define WIN  256
#define KQ   320
#define TT   64
#define NTIL 32
#define GAMMA 0.96875f

// fp16 operands, all single precision.
__device__ __half g_Xh[(size_t)TDIM * CDIM];
__device__ __half g_Wth[(size_t)3 * NW * CDIM];            // [z][n][k]
__device__ __half g_Qh[(size_t)HN * TDIM * CDIM];
__device__ __half g_Kh[(size_t)HN * TDIM * CDIM];
__device__ __half g_Vh[(size_t)HN * TDIM * CDIM];          // [h][t][c]
__device__ __half g_Vth[(size_t)HN * CDIM * TDIM];         // [h][c][t]
__device__ __half g_Ph[(size_t)HN * NTIL * TT * KQ];       // [h][tile][t][q]

// ---------------------------------------------------------------------------
#define CP16(dst, src) \
    asm volatile("cp.async.cg.shared.global [%0], [%1], 16;" :: "r"(dst), "l"(src))
#define CP16Z(dst, src, sz) \
    asm volatile("cp.async.cg.shared.global [%0], [%1], 16, %2;" :: "r"(dst), "l"(src), "r"(sz))
#define CP_COMMIT() asm volatile("cp.async.commit_group;" ::: "memory")
#define CP_WAIT1()  asm volatile("cp.async.wait_group 1;" ::: "memory")
#define CP_WAIT0()  asm volatile("cp.async.wait_group 0;" ::: "memory")

__device__ __forceinline__ uint32_t smem_u32(const void* p) {
    uint32_t a;
    asm("{ .reg .u64 t; cvta.to.shared.u64 t, %1; cvt.u32.u64 %0, t; }"
        : "=r"(a) : "l"(p));
    return a;
}

__device__ __forceinline__ void mma_f16(float c[4], const uint32_t a[4],
                                        const uint32_t b[2]) {
    asm volatile(
        "mma.sync.aligned.m16n8k16.row.col.f32.f16.f16.f32 "
        "{%0,%1,%2,%3}, {%4,%5,%6,%7}, {%8,%9}, {%0,%1,%2,%3};"
        : "+f"(c[0]), "+f"(c[1]), "+f"(c[2]), "+f"(c[3])
        : "r"(a[0]), "r"(a[1]), "r"(a[2]), "r"(a[3]), "r"(b[0]), "r"(b[1]));
}

__device__ __forceinline__ uint32_t pack_h2(float v0, float v1) {
    __half2 h = __floats2half2_rn(v0, v1);
    return *(uint32_t*)&h;
}

// ---------------------------------------------------------------------------
// Prep: X -> fp16
// ---------------------------------------------------------------------------
__global__ __launch_bounds__(256) void prep_x(const float* __restrict__ X)
{
    int i = blockIdx.x * 256 + threadIdx.x;
    float4 v = ((const float4*)X)[i];
    ((uint2*)g_Xh)[i] = make_uint2(pack_h2(v.x, v.y), pack_h2(v.z, v.w));
}

// ---------------------------------------------------------------------------
// Prep: transpose W [K,N] -> Wt [N,K], fp16
// ---------------------------------------------------------------------------
__global__ __launch_bounds__(256) void prep_w(
    const float* __restrict__ Wq, const float* __restrict__ Wk,
    const float* __restrict__ Wv)
{
    const int z = blockIdx.z;
    const float* W = (z == 0) ? Wq : ((z == 1) ? Wk : Wv);
    const int n0 = blockIdx.x * 32;
    const int k0 = blockIdx.y * 32;

    __shared__ float t[32][33];
    const int tx = threadIdx.x, ty = threadIdx.y;
#pragma unroll
    for (int j = 0; j < 4; j++)
        t[ty + 8 * j][tx] = W[(size_t)(k0 + ty + 8 * j) * NW + n0 + tx];
    __syncthreads();
#pragma unroll
    for (int j = 0; j < 4; j++) {
        float v = t[tx][ty + 8 * j];
        size_t o = ((size_t)z * NW + n0 + ty + 8 * j) * CDIM + k0 + tx;
        g_Wth[o] = __float2half_rn(v);
    }
}

// ---------------------------------------------------------------------------
// Projection: single-term fp16, fused RoPE+SiLU, outputs Q/K/V fp16.
// (Round-10/12 exact shape — occ-2 is load-bearing.)
// CTA tile M=128 N=128 Kstage=32, 3-stage pipeline.
// ---------------------------------------------------------------------------
#define PSTAGE 20480
#define SMEM_PROJ (3 * PSTAGE)

__device__ __forceinline__ void proj_load_stage(
    uint32_t stb, int tid, int m0, int zn0, int k0)
{
#pragma unroll
    for (int i = 0; i < 4; i++) {
        const int c = tid + i * 256;
        if (c < 512) {
            const int row = c >> 2;
            const int ch  = c & 3;
            const __half* src = g_Xh + (size_t)(m0 + row) * CDIM + k0 + ch * 8;
            CP16(stb + row * 80 + ch * 16, src);
        } else {
            const int rem = c - 512;
            const int row = rem >> 2;
            const int ch  = rem & 3;
            const __half* src = g_Wth + (size_t)(zn0 + row) * CDIM + k0 + ch * 8;
            CP16(stb + 10240 + row * 80 + ch * 16, src);
        }
    }
}

__global__ __launch_bounds__(256, 2) void proj_mma()
{
    extern __shared__ char smem[];
    const uint32_t sb = smem_u32(smem);
    const int tid = threadIdx.x;
    const int wid = tid >> 5;
    const int lane = tid & 31;
    const int wm = wid & 1, wn = wid >> 1;
    const int g = lane >> 2, t4 = lane & 3;

    const int m0 = blockIdx.x * 128;
    const int n0 = blockIdx.y * 128;
    const int z  = blockIdx.z;
    const int zn0 = z * NW + n0;

    float acc[4][4][4];
#pragma unroll
    for (int i = 0; i < 4; i++)
#pragma unroll
        for (int j = 0; j < 4; j++)
#pragma unroll
            for (int q = 0; q < 4; q++) acc[i][j][q] = 0.f;

    proj_load_stage(sb, tid, m0, zn0, 0);
    CP_COMMIT();
    proj_load_stage(sb + PSTAGE, tid, m0, zn0, 32);
    CP_COMMIT();

#pragma unroll 1
    for (int s = 0; s < 32; s++) {
        if (s < 31) { CP_WAIT1(); } else { CP_WAIT0(); }
        __syncthreads();
        if (s + 2 < 32) {
            proj_load_stage(sb + ((s + 2) % 3) * PSTAGE, tid, m0, zn0, (s + 2) * 32);
            CP_COMMIT();
        }
        const char* st = smem + (s % 3) * PSTAGE;
        const char* Ah = st;
        const char* Bh = st + 10240;

#pragma unroll
        for (int kk = 0; kk < 32; kk += 16) {
            uint32_t ah[4][4];
#pragma unroll
            for (int i = 0; i < 4; i++) {
                const int b0 = (wm * 64 + i * 16 + g) * 80 + kk * 2 + t4 * 4;
                ah[i][0] = *(const uint32_t*)(Ah + b0);
                ah[i][1] = *(const uint32_t*)(Ah + b0 + 640);
                ah[i][2] = *(const uint32_t*)(Ah + b0 + 16);
                ah[i][3] = *(const uint32_t*)(Ah + b0 + 656);
            }
            uint32_t bh[4][2];
#pragma unroll
            for (int j = 0; j < 4; j++) {
                const int bb = (wn * 32 + j * 8 + g) * 80 + kk * 2 + t4 * 4;
                bh[j][0] = *(const uint32_t*)(Bh + bb);
                bh[j][1] = *(const uint32_t*)(Bh + bb + 16);
            }
#pragma unroll
            for (int i = 0; i < 4; i++)
#pragma unroll
                for (int j = 0; j < 4; j++)
                    mma_f16(acc[i][j], ah[i], bh[j]);
        }
    }

    // epilogue: RoPE (Q,K cols<64) + SiLU, fp16 store
    const int h  = n0 >> 10;
    const int cbase = (n0 & 1023) + wn * 32 + 2 * t4;
    const bool rope_blk = (z < 2) && ((n0 & 1023) == 0) && (wn < 2);

    __half* Hi = (z == 0) ? g_Qh : ((z == 1) ? g_Kh : g_Vh);
    Hi += (size_t)h * TDIM * CDIM;

#pragma unroll
    for (int i = 0; i < 4; i++) {
#pragma unroll
        for (int rr = 0; rr < 2; rr++) {
            const int r = m0 + wm * 64 + i * 16 + g + rr * 8;
#pragma unroll
            for (int j = 0; j < 4; j++) {
                const int col = cbase + j * 8;
                float v0 = acc[i][j][2 * rr];
                float v1 = acc[i][j][2 * rr + 1];
                if (rope_blk) {
                    int c2 = col >> 1;
                    float invf = (float)exp(-((double)(2 * c2) / 64.0) * log(10000.0));
                    float ang = (float)r * invf;
                    float sn, cs;
                    sincosf(ang, &sn, &cs);
                    float y0 = v0 * cs - v1 * sn;
                    float y1 = v1 * cs + v0 * sn;
                    v0 = y0; v1 = y1;
                }
                v0 = v0 / (1.f + expf(-v0));
                v1 = v1 / (1.f + expf(-v1));
                ((uint32_t*)Hi)[((size_t)r * CDIM + col) >> 1] = pack_h2(v0, v1);
            }
        }
    }
}

// ---------------------------------------------------------------------------
// V transpose: [h][t][c] -> [h][c][t]
// ---------------------------------------------------------------------------
__global__ void transpose_v()
{
    __shared__ unsigned short sh[32][33];
    const int c0 = blockIdx.x * 32;
    const int t0 = blockIdx.y * 32;
    const int h  = blockIdx.z;
    const int tx = threadIdx.x, ty = threadIdx.y;

    const unsigned short* Vh = (const unsigned short*)g_Vh + (size_t)h * TDIM * CDIM;
#pragma unroll
    for (int k = 0; k < 4; k++) {
        int r = ty + 8 * k;
        sh[r][tx] = Vh[(size_t)(t0 + r) * CDIM + c0 + tx];
    }
    __syncthreads();
    unsigned short* Th = (unsigned short*)g_Vth + (size_t)h * CDIM * TDIM;
#pragma unroll
    for (int k = 0; k < 4; k++) {
        int r = ty + 8 * k;
        Th[(size_t)(c0 + r) * TDIM + t0 + tx] = sh[tx][r];
    }
}

// ---------------------------------------------------------------------------
// qk_mma: P = decay * (K Q^T), single-term fp16, Kstage=64.
// M=64(t) N=160(q) per block, grid.x=2 covers q in [t0, t0+320), K=1024.
// Warp tile M=32, N=40 (5 j-blocks).
// stage: A[64][144B]@0 (9216) | B[160][144B]@9216 (23040); stage 32256.
// ---------------------------------------------------------------------------
#define QKSTAGE 32256
#define SMEM_QK (3 * QKSTAGE)

__global__ __launch_bounds__(256, 2) void qk_mma()
{
    extern __shared__ char smem[];
    const uint32_t sb = smem_u32(smem);
    const int tid = threadIdx.x;
    const int wid = tid >> 5;
    const int lane = tid & 31;
    const int wm = wid & 1, wn = wid >> 1;
    const int g = lane >> 2, t4 = lane & 3;

    const int qc   = blockIdx.x;          // 0..1
    const int tile = blockIdx.y;
    const int h    = blockIdx.z;
    const int t0   = tile * TT;
    const int q0   = t0 + qc * 160;

    const __half* Kh = g_Kh + (size_t)h * TDIM * CDIM;
    const __half* Qh = g_Qh + (size_t)h * TDIM * CDIM;

    float acc[2][5][4];
#pragma unroll
    for (int i = 0; i < 2; i++)
#pragma unroll
        for (int j = 0; j < 5; j++)
#pragma unroll
            for (int q = 0; q < 4; q++) acc[i][j][q] = 0.f;

    auto load_stage = [&](int s, uint32_t stb) {
        const int k0 = s * 64;
#pragma unroll
        for (int i = 0; i < 7; i++) {
            const int c = tid + i * 256;
            if (c < 512) {
                const int row = c >> 3, ch = c & 7;
                const __half* src = Kh + (size_t)(t0 + row) * CDIM + k0 + ch * 8;
                CP16(stb + row * 144 + ch * 16, src);
            } else {
                const int rem = c - 512;                 // 0..1279
                const int row = rem >> 3, ch = rem & 7;  // row 0..159
                int q = q0 + row;
                int sz = (q < TDIM) ? 16 : 0;
                if (q >= TDIM) q = 0;
                const __half* src = Qh + (size_t)q * CDIM + k0 + ch * 8;
                CP16Z(stb + 9216 + row * 144 + ch * 16, src, sz);
            }
        }
    };

    load_stage(0, sb);
    CP_COMMIT();
    load_stage(1, sb + QKSTAGE);
    CP_COMMIT();

#pragma unroll 1
    for (int s = 0; s < 16; s++) {
        if (s < 15) { CP_WAIT1(); } else { CP_WAIT0(); }
        __syncthreads();
        if (s + 2 < 16) {
            load_stage(s + 2, sb + ((s + 2) % 3) * QKSTAGE);
            CP_COMMIT();
        }
        const char* st = smem + (s % 3) * QKSTAGE;
        const char* Ah = st;
        const char* Bh = st + 9216;

#pragma unroll
        for (int kk = 0; kk < 64; kk += 16) {
            uint32_t ah[2][4];
#pragma unroll
            for (int i = 0; i < 2; i++) {
                const int b0 = (wm * 32 + i * 16 + g) * 144 + kk * 2 + t4 * 4;
                ah[i][0] = *(const uint32_t*)(Ah + b0);
                ah[i][1] = *(const uint32_t*)(Ah + b0 + 1152);
                ah[i][2] = *(const uint32_t*)(Ah + b0 + 16);
                ah[i][3] = *(const uint32_t*)(Ah + b0 + 1168);
            }
            uint32_t bh[5][2];
#pragma unroll
            for (int j = 0; j < 5; j++) {
                const int bb = (wn * 40 + j * 8 + g) * 144 + kk * 2 + t4 * 4;
                bh[j][0] = *(const uint32_t*)(Bh + bb);
                bh[j][1] = *(const uint32_t*)(Bh + bb + 16);
            }
#pragma unroll
            for (int i = 0; i < 2; i++)
#pragma unroll
                for (int j = 0; j < 5; j++)
                    mma_f16(acc[i][j], ah[i], bh[j]);
        }
    }

    // epilogue: decay + mask, fp16 store P
    const float lg = log2f(GAMMA);
    __half* Phb = g_Ph + ((size_t)h * NTIL + tile) * TT * KQ;
#pragma unroll
    for (int i = 0; i < 2; i++) {
#pragma unroll
        for (int rr = 0; rr < 2; rr++) {
            const int tl = wm * 32 + i * 16 + g + rr * 8;
            const int t  = t0 + tl;
#pragma unroll
            for (int j = 0; j < 5; j++) {
                const int ql = qc * 160 + wn * 40 + j * 8 + 2 * t4;
                const int q  = t0 + ql;
                float v0 = acc[i][j][2 * rr];
                float v1 = acc[i][j][2 * rr + 1];
                int wd0 = q - t, wd1 = wd0 + 1;
                v0 = (wd0 >= 0 && wd0 < WIN && q < TDIM)
                     ? v0 * exp2f((float)wd0 * lg) : 0.f;
                v1 = (wd1 >= 0 && wd1 < WIN && (q + 1) < TDIM)
                     ? v1 * exp2f((float)wd1 * lg) : 0.f;
                ((uint32_t*)Phb)[((size_t)tl * KQ + ql) >> 1] = pack_h2(v0, v1);
            }
        }
    }
}

// ---------------------------------------------------------------------------
// av_mma: out[t][c] = sum_{h,q} P * V, single-term fp16, Kstage=64.
// M=64(t) N=128(c), K = 8*320 = 2560 in 40 stages (320 = 5*64, clean).
// stage: A[64][144B]@0 (9216) | B[128][144B]@9216 (18432); stage 27648.
// ---------------------------------------------------------------------------
#define AVSTAGE 27648
#define SMEM_AV (3 * AVSTAGE)

__global__ __launch_bounds__(256, 2) void av_mma(float* __restrict__ out)
{
    extern __shared__ char smem[];
    const uint32_t sb = smem_u32(smem);
    const int tid = threadIdx.x;
    const int wid = tid >> 5;
    const int lane = tid & 31;
    const int wm = wid & 1, wn = wid >> 1;
    const int g = lane >> 2, t4 = lane & 3;

    const int cc   = blockIdx.x;      // 0..7
    const int tile = blockIdx.y;
    const int t0   = tile * TT;
    const int c0   = cc * 128;

    float acc[2][4][4];
#pragma unroll
    for (int i = 0; i < 2; i++)
#pragma unroll
        for (int j = 0; j < 4; j++)
#pragma unroll
            for (int q = 0; q < 4; q++) acc[i][j][q] = 0.f;

    auto load_stage = [&](int s, uint32_t stb) {
        const int kk0 = s * 64;
        const int h   = kk0 / KQ;
        const int ql  = kk0 - h * KQ;
#pragma unroll
        for (int i = 0; i < 6; i++) {
            const int c = tid + i * 256;
            if (c < 512) {
                const int row = c >> 3, ch = c & 7;
                const __half* src = g_Ph
                    + ((size_t)h * NTIL + tile) * TT * KQ
                    + (size_t)row * KQ + ql + ch * 8;
                CP16(stb + row * 144 + ch * 16, src);
            } else {
                const int rem = c - 512;
                const int row = rem >> 3, ch = rem & 7;  // row 0..127 (c-dim)
                int tg = t0 + ql + ch * 8;
                int sz = (tg < TDIM) ? 16 : 0;
                if (tg >= TDIM) tg = 0;
                const __half* src = g_Vth
                    + ((size_t)h * CDIM + c0 + row) * TDIM + tg;
                CP16Z(stb + 9216 + row * 144 + ch * 16, src, sz);
            }
        }
    };

    load_stage(0, sb);
    CP_COMMIT();
    load_stage(1, sb + AVSTAGE);
    CP_COMMIT();

#pragma unroll 1
    for (int s = 0; s < 40; s++) {
        if (s < 39) { CP_WAIT1(); } else { CP_WAIT0(); }
        __syncthreads();
        if (s + 2 < 40) {
            load_stage(s + 2, sb + ((s + 2) % 3) * AVSTAGE);
            CP_COMMIT();
        }
        const char* st = smem + (s % 3) * AVSTAGE;
        const char* Ah = st;
        const char* Bh = st + 9216;

#pragma unroll
        for (int kk = 0; kk < 64; kk += 16) {
            uint32_t ah[2][4];
#pragma unroll
            for (int i = 0; i < 2; i++) {
                const int b0 = (wm * 32 + i * 16 + g) * 144 + kk * 2 + t4 * 4;
                ah[i][0] = *(const uint32_t*)(Ah + b0);
                ah[i][1] = *(const uint32_t*)(Ah + b0 + 1152);
                ah[i][2] = *(const uint32_t*)(Ah + b0 + 16);
                ah[i][3] = *(const uint32_t*)(Ah + b0 + 1168);
            }
            uint32_t bh[4][2];
#pragma unroll
            for (int j = 0; j < 4; j++) {
                const int bb = (wn * 32 + j * 8 + g) * 144 + kk * 2 + t4 * 4;
                bh[j][0] = *(const uint32_t*)(Bh + bb);
                bh[j][1] = *(const uint32_t*)(Bh + bb + 16);
            }
#pragma unroll
            for (int i = 0; i < 2; i++)
#pragma unroll
                for (int j = 0; j < 4; j++)
                    mma_f16(acc[i][j], ah[i], bh[j]);
        }
    }

    // epilogue: fp32 out
#pragma unroll
    for (int i = 0; i < 2; i++) {
#pragma unroll
        for (int rr = 0; rr < 2; rr++) {
            const int t = t0 + wm * 32 + i * 16 + g + rr * 8;
#pragma unroll
            for (int j = 0; j < 4; j++) {
                const int c = c0 + wn * 32 + j * 8 + 2 * t4;
                *(float2*)(out + (size_t)t * CDIM + c) =
                    make_float2(acc[i][j][2 * rr], acc[i][j][2 * rr + 1]);
            }
        }
    }
}

// ---------------------------------------------------------------------------
// GroupNorm in place on out
// ---------------------------------------------------------------------------
__global__ __launch_bounds__(256) void gn_kernel(
    float* __restrict__ out,
    const float* __restrict__ wgt,
    const float* __restrict__ bias)
{
    const int t = blockIdx.x;
    const int tid = threadIdx.x;

    float4 v = *(float4*)(out + (size_t)t * CDIM + tid * 4);
    float s  = v.x + v.y + v.z + v.w;
    float sq = v.x * v.x + v.y * v.y + v.z * v.z + v.w * v.w;

#pragma unroll
    for (int off = 8; off > 0; off >>= 1) {
        s  += __shfl_down_sync(0xffffffffu, s,  off, 16);
        sq += __shfl_down_sync(0xffffffffu, sq, off, 16);
    }
    s  = __shfl_sync(0xffffffffu, s,  0, 16);
    sq = __shfl_sync(0xffffffffu, sq, 0, 16);

    float mean = s * (1.f / 64.f);
    float var  = sq * (1.f / 64.f) - mean * mean;
    float rs   = rsqrtf(var + 1e-5f);

    float4 w4 = *(const float4*)(wgt + tid * 4);
    float4 b4 = *(const float4*)(bias + tid * 4);
    v.x = (v.x - mean) * rs * w4.x + b4.x;
    v.y = (v.y - mean) * rs * w4.y + b4.y;
    v.z = (v.z - mean) * rs * w4.z + b4.z;
    v.w = (v.w - mean) * rs * w4.w + b4.w;
    *(float4*)(out + (size_t)t * CDIM + tid * 4) = v;
}

// ---------------------------------------------------------------------------
extern "C" void kernel_launch(void* const* d_in, const int* in_sizes, int n_in,
                              void* d_out, int out_size)
{
    const float* X  = (const float*)d_in[0];
    const float* Wq = (const float*)d_in[1];
    const float* Wk = (const float*)d_in[2];
    const float* Wv = (const float*)d_in[3];
    const float* gw = (const float*)d_in[4];
    const float* gb = (const float*)d_in[5];
    float* out = (float*)d_out;

    prep_x<<<(TDIM * CDIM / 4) / 256, 256>>>(X);
    prep_w<<<dim3(NW / 32, CDIM / 32, 3), dim3(32, 8)>>>(Wq, Wk, Wv);

    cudaFuncSetAttribute(proj_mma, cudaFuncAttributeMaxDynamicSharedMemorySize,
                         SMEM_PROJ);
    proj_mma<<<dim3(16, 64, 3), 256, SMEM_PROJ>>>();

    transpose_v<<<dim3(CDIM / 32, TDIM / 32, HN), dim3(32, 8)>>>();

    cudaFuncSetAttribute(qk_mma, cudaFuncAttributeMaxDynamicSharedMemorySize,
                         SMEM_QK);
    qk_mma<<<dim3(2, NTIL, HN), 256, SMEM_QK>>>();

    cudaFuncSetAttribute(av_mma, cudaFuncAttributeMaxDynamicSharedMemorySize,
                         SMEM_AV);
    av_mma<<<dim3(8, NTIL), 256, SMEM_AV>>>(out);

    gn_kernel<<<TDIM, 256>>>(out, gw, gb);
}